// round 17
// baseline (speedup 1.0000x reference)
#include <cuda_runtime.h>
#include <cuda_bf16.h>

#define N_NODES 10000
#define N_EDGES 320000
#define IN_DIM  128
#define HID     256
#define HID4    1024
#define NSH     4        // cursor shards per node
#define SUBCAP  64       // per-shard bucket capacity: Poisson(8), 64 = +20 sigma

// ---------------- scratch (static device globals; no allocation) ----------------
__device__ float g_W[HID * HID];        // evolved GCN weight                 [H, H]
__device__ float g_Wc[IN_DIM * HID];    // Wp @ W                             [IN, H]
__device__ float g_bc[HID];             // bp @ W                             [H]
__device__ float g_y[N_NODES * IN_DIM]; // aggregated scaled features        [N, IN]
__device__ float g_u[N_NODES];          // dinv[i] + sum_in dinv[s]
__device__ float g_dinv[N_NODES];       // rsqrt(deg+1), written by gather
__device__ int   g_cur[N_NODES * NSH];  // sharded fill cursors (zeroed at load, re-zeroed per call)
__device__ int   g_bkt[N_NODES * NSH * SUBCAP];  // per-dst sharded src buckets

// ---------------- streams/events (created at static init) ----------------
static cudaStream_t g_s2 = nullptr, g_s3 = nullptr;
static cudaEvent_t g_evFork = nullptr, g_evJoin = nullptr, g_evW = nullptr;
static cudaEvent_t g_evBC = nullptr, g_evG = nullptr, g_evCR = nullptr;
namespace {
struct StreamInit {
    StreamInit() {
        cudaStreamCreateWithFlags(&g_s2, cudaStreamNonBlocking);
        cudaStreamCreateWithFlags(&g_s3, cudaStreamNonBlocking);
        cudaEventCreateWithFlags(&g_evFork, cudaEventDisableTiming);
        cudaEventCreateWithFlags(&g_evJoin, cudaEventDisableTiming);
        cudaEventCreateWithFlags(&g_evW, cudaEventDisableTiming);
        cudaEventCreateWithFlags(&g_evBC, cudaEventDisableTiming);
        cudaEventCreateWithFlags(&g_evG, cudaEventDisableTiming);
        cudaEventCreateWithFlags(&g_evCR, cudaEventDisableTiming);
    }
};
static StreamInit g_si;
}

__device__ __forceinline__ float tanh_fast(float x) {
    float r;
    asm("tanh.approx.f32 %0, %1;" : "=f"(r) : "f"(x));
    return r;
}
__device__ __forceinline__ float sig_fast(float x) {
    return 0.5f * tanh_fast(0.5f * x) + 0.5f;
}
// total degree from a node's 4 shard cursors (clamped)
__device__ __forceinline__ int deg_of(int n) {
    const int4 c = *reinterpret_cast<const int4*>(g_cur + n * NSH);
    return min(c.x, SUBCAP) + min(c.y, SUBCAP) + min(c.z, SUBCAP) + min(c.w, SUBCAP);
}

// ---------------- graph prologue ----------------
// 2 edges per thread (int2 loads), 625 blocks -> ~50% occupancy + ILP 2 on the
// ATOMG chain; shard = global edge index & 3 (same distribution as before)
__global__ void k_fill(const int* __restrict__ ei) {
    int t = blockIdx.x * blockDim.x + threadIdx.x;
    if (t >= N_EDGES / 2) return;
    int2 s2 = *reinterpret_cast<const int2*>(ei + t * 2);
    int2 d2 = *reinterpret_cast<const int2*>(ei + N_EDGES + t * 2);
    int e0 = t * 2;
    int slot0 = d2.x * NSH + (e0 & 3);
    int slot1 = d2.y * NSH + ((e0 + 1) & 3);
    int pos0 = atomicAdd(&g_cur[slot0], 1);
    int pos1 = atomicAdd(&g_cur[slot1], 1);
    if (pos0 < SUBCAP) g_bkt[slot0 * SUBCAP + pos0] = s2.x;
    if (pos1 < SUBCAP) g_bkt[slot1 * SUBCAP + pos1] = s2.y;
}

// one warp per dst node:
// y[i,:] = x[i,:]*dinv[i] + sum_{s in N(i)} x[s,:]*dinv[s]
// u[i]   = dinv[i] + sum dinv[s];  also stores dinv[i] for the GEMM epilogue
__global__ void k_gather(const float4* __restrict__ x4) {
    int n = (blockIdx.x * blockDim.x + threadIdx.x) >> 5;
    int lane = threadIdx.x & 31;
    if (n >= N_NODES) return;

    const int4 c4 = *reinterpret_cast<const int4*>(g_cur + n * NSH);
    const int cs[4] = {min(c4.x, SUBCAP), min(c4.y, SUBCAP), min(c4.z, SUBCAP), min(c4.w, SUBCAP)};
    const int deg = cs[0] + cs[1] + cs[2] + cs[3];

    float di = rsqrtf((float)deg + 1.0f);
    float4 xv = __ldg(x4 + (size_t)n * 32 + lane);
    float4 acc = make_float4(xv.x * di, xv.y * di, xv.z * di, xv.w * di);
    float tsum = di;

    #pragma unroll
    for (int sh = 0; sh < NSH; sh++) {
        const int* bkt = g_bkt + ((size_t)n * NSH + sh) * SUBCAP;
        const int mt = cs[sh];
        for (int c = 0; c < mt; c += 32) {
            int m = min(32, mt - c);
            int idx = 0;
            float dv = 0.0f;
            if (lane < m) {
                idx = __ldg(bkt + c + lane);
                dv = rsqrtf((float)deg_of(idx) + 1.0f);
            }
            int j = 0;
            for (; j + 4 <= m; j += 4) {
                int s0 = __shfl_sync(0xffffffffu, idx, j);
                int s1 = __shfl_sync(0xffffffffu, idx, j + 1);
                int s2 = __shfl_sync(0xffffffffu, idx, j + 2);
                int s3 = __shfl_sync(0xffffffffu, idx, j + 3);
                float w0 = __shfl_sync(0xffffffffu, dv, j);
                float w1 = __shfl_sync(0xffffffffu, dv, j + 1);
                float w2 = __shfl_sync(0xffffffffu, dv, j + 2);
                float w3 = __shfl_sync(0xffffffffu, dv, j + 3);
                float4 v0 = __ldg(x4 + (size_t)s0 * 32 + lane);
                float4 v1 = __ldg(x4 + (size_t)s1 * 32 + lane);
                float4 v2 = __ldg(x4 + (size_t)s2 * 32 + lane);
                float4 v3 = __ldg(x4 + (size_t)s3 * 32 + lane);
                acc.x = fmaf(v0.x, w0, acc.x); acc.y = fmaf(v0.y, w0, acc.y);
                acc.z = fmaf(v0.z, w0, acc.z); acc.w = fmaf(v0.w, w0, acc.w);
                acc.x = fmaf(v1.x, w1, acc.x); acc.y = fmaf(v1.y, w1, acc.y);
                acc.z = fmaf(v1.z, w1, acc.z); acc.w = fmaf(v1.w, w1, acc.w);
                acc.x = fmaf(v2.x, w2, acc.x); acc.y = fmaf(v2.y, w2, acc.y);
                acc.z = fmaf(v2.z, w2, acc.z); acc.w = fmaf(v2.w, w2, acc.w);
                acc.x = fmaf(v3.x, w3, acc.x); acc.y = fmaf(v3.y, w3, acc.y);
                acc.z = fmaf(v3.z, w3, acc.z); acc.w = fmaf(v3.w, w3, acc.w);
                tsum += w0 + w1 + w2 + w3;
            }
            for (; j < m; j++) {
                int s = __shfl_sync(0xffffffffu, idx, j);
                float ws = __shfl_sync(0xffffffffu, dv, j);
                float4 v = __ldg(x4 + (size_t)s * 32 + lane);
                acc.x = fmaf(v.x, ws, acc.x); acc.y = fmaf(v.y, ws, acc.y);
                acc.z = fmaf(v.z, ws, acc.z); acc.w = fmaf(v.w, ws, acc.w);
                tsum += ws;
            }
        }
    }

    reinterpret_cast<float4*>(g_y)[(size_t)n * 32 + lane] = acc;
    if (lane == 0) { g_u[n] = tsum; g_dinv[n] = di; }
}

// ---------------- fused gates GEMM + LSTM evolve ----------------
// W[r, j] = sig(o)*tanh( sig(f)*IW[r,j] + sig(i)*tanh(g) ), gates from
// IW @ (W_ih+W_hh)^T + (b_ih+b_hh). Tile: 64 rows x 16 j x 4 gates. Grid (H/16, H/64).
__global__ void k_gates_evolve(const float* __restrict__ IW,
                               const float* __restrict__ W_ih, const float* __restrict__ W_hh,
                               const float* __restrict__ b_ih, const float* __restrict__ b_hh) {
    __shared__ float As[16][68];
    __shared__ float Bs[16][68];
    const int tx = threadIdx.x, ty = threadIdx.y;   // 16 x 16
    const int tid = ty * 16 + tx;
    const int row0 = blockIdx.y * 64;
    const int j0 = blockIdx.x * 16;
    const int K = HID;

    const int ar = tid >> 2;
    const int akq = (tid & 3) * 4;
    const float* Ap = IW + (size_t)(row0 + ar) * K + akq;

    const int bc = tid >> 2;
    const int bkq = (tid & 3) * 4;
    const int brow = (bc & 3) * HID + (j0 + (bc >> 2));
    const float* Bih = W_ih + (size_t)brow * K + bkq;
    const float* Bhh = W_hh + (size_t)brow * K + bkq;

    float acc[4][4] = {};

    float4 aR = *reinterpret_cast<const float4*>(Ap);
    float4 b1R = *reinterpret_cast<const float4*>(Bih);
    float4 b2R = *reinterpret_cast<const float4*>(Bhh);

    for (int kt = 0; kt < K; kt += 16) {
        As[akq + 0][ar] = aR.x; As[akq + 1][ar] = aR.y;
        As[akq + 2][ar] = aR.z; As[akq + 3][ar] = aR.w;
        Bs[bkq + 0][bc] = b1R.x + b2R.x;
        Bs[bkq + 1][bc] = b1R.y + b2R.y;
        Bs[bkq + 2][bc] = b1R.z + b2R.z;
        Bs[bkq + 3][bc] = b1R.w + b2R.w;
        __syncthreads();

        if (kt + 16 < K) {
            int kn = kt + 16;
            aR  = *reinterpret_cast<const float4*>(Ap + kn);
            b1R = *reinterpret_cast<const float4*>(Bih + kn);
            b2R = *reinterpret_cast<const float4*>(Bhh + kn);
        }

        #pragma unroll
        for (int k = 0; k < 16; k++) {
            float4 a = *reinterpret_cast<const float4*>(&As[k][ty * 4]);
            float4 b = *reinterpret_cast<const float4*>(&Bs[k][tx * 4]);
            float av[4] = {a.x, a.y, a.z, a.w};
            float bv[4] = {b.x, b.y, b.z, b.w};
            #pragma unroll
            for (int i = 0; i < 4; i++)
                #pragma unroll
                for (int j = 0; j < 4; j++)
                    acc[i][j] = fmaf(av[i], bv[j], acc[i][j]);
        }
        __syncthreads();
    }

    const int j = j0 + tx;
    const float bi = b_ih[0 * HID + j] + b_hh[0 * HID + j];
    const float bf = b_ih[1 * HID + j] + b_hh[1 * HID + j];
    const float bg = b_ih[2 * HID + j] + b_hh[2 * HID + j];
    const float bo = b_ih[3 * HID + j] + b_hh[3 * HID + j];
    #pragma unroll
    for (int i = 0; i < 4; i++) {
        int row = row0 + ty * 4 + i;
        float ig = sig_fast(acc[i][0] + bi);
        float fg = sig_fast(acc[i][1] + bf);
        float gg = tanh_fast(acc[i][2] + bg);
        float og = sig_fast(acc[i][3] + bo);
        float c = fg * IW[(size_t)row * HID + j] + ig * gg;
        g_W[(size_t)row * HID + j] = og * tanh_fast(c);
    }
}

// bc[j] = sum_k bp[k] * W[k, j]   (16 blocks x 256 threads, 16-way k split)
__global__ void k_bc(const float* __restrict__ bp) {
    __shared__ float red[16][17];
    int c  = threadIdx.x & 15;
    int kk = threadIdx.x >> 4;
    int col = blockIdx.x * 16 + c;
    float acc = 0.0f;
    #pragma unroll
    for (int t = 0; t < 16; t++) {
        int k = kk + t * 16;
        acc += bp[k] * g_W[k * HID + col];
    }
    red[kk][c] = acc;
    __syncthreads();
    if (kk == 0) {
        float s = 0.0f;
        #pragma unroll
        for (int t = 0; t < 16; t++) s += red[t][c];
        g_bc[col] = s;
    }
}

// ---------------- Wc GEMM, split-K: g_Wc += Wp[kchunk] @ g_W[kchunk] ----------------
// 32x64 tiles, split-K(4): grid (HID/64=4, IN_DIM/32=4, 4) = 64 blocks.
__global__ void k_wc_gemm(const float* __restrict__ A) {
    __shared__ float As[16][36];
    __shared__ float Bs[16][68];
    const int tid = threadIdx.x;            // 256 threads
    const int tx = tid & 15;
    const int ty = tid >> 4;                // 0..15 -> 2 rows each
    const int row0 = blockIdx.y * 32;
    const int col0 = blockIdx.x * 64;
    const int kbase = blockIdx.z * 64;
    const int N = HID, K = HID;

    const int ar = (tid & 127) >> 2;
    const int akq = (tid & 3) * 4;
    const bool aload = tid < 128;
    const float* Ap = A + (size_t)(row0 + ar) * K + kbase + akq;
    const int bk = tid >> 4;
    const int bcq = (tid & 15) * 4;
    const float* Bp = g_W + (size_t)(kbase + bk) * N + col0 + bcq;

    float acc[2][4] = {};

    float4 aR = aload ? *reinterpret_cast<const float4*>(Ap) : make_float4(0.f, 0.f, 0.f, 0.f);
    float4 bR = *reinterpret_cast<const float4*>(Bp);

    #pragma unroll
    for (int kt = 0; kt < 64; kt += 16) {
        if (aload) {
            As[akq + 0][ar] = aR.x; As[akq + 1][ar] = aR.y;
            As[akq + 2][ar] = aR.z; As[akq + 3][ar] = aR.w;
        }
        *reinterpret_cast<float4*>(&Bs[bk][bcq]) = bR;
        __syncthreads();

        if (kt + 16 < 64) {
            int kn = kt + 16;
            if (aload) aR = *reinterpret_cast<const float4*>(Ap + kn);
            bR = *reinterpret_cast<const float4*>(Bp + (size_t)kn * N);
        }

        #pragma unroll
        for (int k = 0; k < 16; k++) {
            float a0 = As[k][ty * 2];
            float a1 = As[k][ty * 2 + 1];
            float4 b = *reinterpret_cast<const float4*>(&Bs[k][tx * 4]);
            acc[0][0] = fmaf(a0, b.x, acc[0][0]); acc[0][1] = fmaf(a0, b.y, acc[0][1]);
            acc[0][2] = fmaf(a0, b.z, acc[0][2]); acc[0][3] = fmaf(a0, b.w, acc[0][3]);
            acc[1][0] = fmaf(a1, b.x, acc[1][0]); acc[1][1] = fmaf(a1, b.y, acc[1][1]);
            acc[1][2] = fmaf(a1, b.z, acc[1][2]); acc[1][3] = fmaf(a1, b.w, acc[1][3]);
        }
        __syncthreads();
    }

    #pragma unroll
    for (int i = 0; i < 2; i++) {
        int row = row0 + ty * 2 + i;
        float* dst = g_Wc + (size_t)row * HID + col0 + tx * 4;
        asm volatile("red.global.add.v4.f32 [%0], {%1,%2,%3,%4};"
                     :: "l"(dst), "f"(acc[i][0]), "f"(acc[i][1]), "f"(acc[i][2]), "f"(acc[i][3])
                     : "memory");
    }
}

// ---------------- main GEMM (f32x2 packed FMA, software-pipelined) ----------------
__global__ void k_main_gemm(const float* __restrict__ bgcn, float* __restrict__ out) {
    __shared__ float As[16][132];
    __shared__ float Bs[16][68];
    const int tid = threadIdx.x;           // 256 threads
    const int tx = tid & 15;
    const int ty = tid >> 4;
    const int row0 = blockIdx.y * 128;
    const int col0 = blockIdx.x * 64;
    const int M = N_NODES, N = HID, K = IN_DIM;

    const int ar0 = tid >> 2, ar1 = (tid + 256) >> 2;
    const int akq = (tid & 3) * 4;
    const int arow0 = row0 + ar0, arow1 = row0 + ar1;
    const bool aok0 = arow0 < M, aok1 = arow1 < M;
    const float* Ap0 = g_y + (size_t)(aok0 ? arow0 : 0) * K + akq;
    const float* Ap1 = g_y + (size_t)(aok1 ? arow1 : 0) * K + akq;
    const int bk = tid >> 4;
    const int bcq = (tid & 15) * 4;
    const float* Bp = g_Wc + (size_t)bk * N + col0 + bcq;

    unsigned long long acc2[4][4] = {};

    float4 aR0 = aok0 ? *reinterpret_cast<const float4*>(Ap0) : make_float4(0.f, 0.f, 0.f, 0.f);
    float4 aR1 = aok1 ? *reinterpret_cast<const float4*>(Ap1) : make_float4(0.f, 0.f, 0.f, 0.f);
    float4 bRv = *reinterpret_cast<const float4*>(Bp);

    for (int kt = 0; kt < K; kt += 16) {
        As[akq + 0][ar0] = aR0.x; As[akq + 1][ar0] = aR0.y;
        As[akq + 2][ar0] = aR0.z; As[akq + 3][ar0] = aR0.w;
        As[akq + 0][ar1] = aR1.x; As[akq + 1][ar1] = aR1.y;
        As[akq + 2][ar1] = aR1.z; As[akq + 3][ar1] = aR1.w;
        *reinterpret_cast<float4*>(&Bs[bk][bcq]) = bRv;
        __syncthreads();

        if (kt + 16 < K) {
            int knext = kt + 16;
            aR0 = aok0 ? *reinterpret_cast<const float4*>(Ap0 + knext) : make_float4(0.f, 0.f, 0.f, 0.f);
            aR1 = aok1 ? *reinterpret_cast<const float4*>(Ap1 + knext) : make_float4(0.f, 0.f, 0.f, 0.f);
            bRv = *reinterpret_cast<const float4*>(Bp + (size_t)knext * N);
        }

        #pragma unroll
        for (int k = 0; k < 16; k++) {
            unsigned long long ap[4];
            #pragma unroll
            for (int i2 = 0; i2 < 4; i2++)
                ap[i2] = *reinterpret_cast<const unsigned long long*>(&As[k][ty * 8 + 2 * i2]);
            float4 b = *reinterpret_cast<const float4*>(&Bs[k][tx * 4]);
            unsigned long long bp0, bp1, bp2, bp3;
            asm("mov.b64 %0, {%1, %1};" : "=l"(bp0) : "f"(b.x));
            asm("mov.b64 %0, {%1, %1};" : "=l"(bp1) : "f"(b.y));
            asm("mov.b64 %0, {%1, %1};" : "=l"(bp2) : "f"(b.z));
            asm("mov.b64 %0, {%1, %1};" : "=l"(bp3) : "f"(b.w));
            #pragma unroll
            for (int i2 = 0; i2 < 4; i2++) {
                asm("fma.rn.f32x2 %0, %1, %2, %0;" : "+l"(acc2[i2][0]) : "l"(ap[i2]), "l"(bp0));
                asm("fma.rn.f32x2 %0, %1, %2, %0;" : "+l"(acc2[i2][1]) : "l"(ap[i2]), "l"(bp1));
                asm("fma.rn.f32x2 %0, %1, %2, %0;" : "+l"(acc2[i2][2]) : "l"(ap[i2]), "l"(bp2));
                asm("fma.rn.f32x2 %0, %1, %2, %0;" : "+l"(acc2[i2][3]) : "l"(ap[i2]), "l"(bp3));
            }
        }
        __syncthreads();
    }

    const int col = col0 + tx * 4;
    const float4 bc4 = *reinterpret_cast<const float4*>(g_bc + col);
    const float4 bg4 = *reinterpret_cast<const float4*>(bgcn + col);
    #pragma unroll
    for (int i2 = 0; i2 < 4; i2++) {
        float lo[4], hi[4];
        #pragma unroll
        for (int j = 0; j < 4; j++)
            asm("mov.b64 {%0, %1}, %2;" : "=f"(lo[j]), "=f"(hi[j]) : "l"(acc2[i2][j]));
        #pragma unroll
        for (int h = 0; h < 2; h++) {
            int row = row0 + ty * 8 + 2 * i2 + h;
            if (row >= M) continue;
            float* a = h ? hi : lo;
            float sc = g_dinv[row];
            float uu = g_u[row] * sc;
            float4 v;
            v.x = a[0] * sc + bc4.x * uu + bg4.x;
            v.y = a[1] * sc + bc4.y * uu + bg4.y;
            v.z = a[2] * sc + bc4.z * uu + bg4.z;
            v.w = a[3] * sc + bc4.w * uu + bg4.w;
            *reinterpret_cast<float4*>(out + (size_t)row * N + col) = v;
        }
    }
}

// ---------------- launch ----------------
extern "C" void kernel_launch(void* const* d_in, const int* in_sizes, int n_in,
                              void* d_out, int out_size) {
    const float* x    = (const float*)d_in[0];
    const int*   ei   = (const int*)d_in[1];      // jax int64 is silently int32 (x64 disabled)
    const float* Wp   = (const float*)d_in[2];
    const float* bp   = (const float*)d_in[3];
    const float* W_ih = (const float*)d_in[4];
    const float* W_hh = (const float*)d_in[5];
    const float* b_ih = (const float*)d_in[6];
    const float* b_hh = (const float*)d_in[7];
    const float* IW   = (const float*)d_in[8];
    const float* bgcn = (const float*)d_in[9];
    float* out = (float*)d_out;

    int*   d_cur; cudaGetSymbolAddress((void**)&d_cur, g_cur);
    float* d_Wc;  cudaGetSymbolAddress((void**)&d_Wc, g_Wc);

    dim3 thr(16, 16);

    cudaEventRecord(g_evFork, 0);

    // stream2: zero Wc, fused gates+evolve, then split-K Wc GEMM
    cudaStreamWaitEvent(g_s2, g_evFork, 0);
    cudaMemsetAsync(d_Wc, 0, IN_DIM * HID * sizeof(float), g_s2);
    k_gates_evolve<<<dim3(HID / 16, HID / 64), thr, 0, g_s2>>>(IW, W_ih, W_hh, b_ih, b_hh);
    cudaEventRecord(g_evW, g_s2);
    k_wc_gemm<<<dim3(HID / 64, IN_DIM / 32, 4), 256, 0, g_s2>>>(Wp);
    cudaEventRecord(g_evJoin, g_s2);

    // stream3: k_bc after evolve, parallel with Wc GEMM (only needs g_W)
    cudaStreamWaitEvent(g_s3, g_evW, 0);
    k_bc<<<16, 256, 0, g_s3>>>(bp);
    cudaEventRecord(g_evBC, g_s3);

    // graph chain on default stream — cursors already zero (module load / prior reset)
    k_fill<<<(N_EDGES / 2 + 255) / 256, 256>>>(ei);
    k_gather<<<(N_NODES * 32 + 255) / 256, 256>>>((const float4*)x);
    cudaEventRecord(g_evG, 0);

    // reset cursors for the next call on s3 (overlaps the main GEMM)
    cudaStreamWaitEvent(g_s3, g_evG, 0);
    cudaMemsetAsync(d_cur, 0, N_NODES * NSH * sizeof(int), g_s3);
    cudaEventRecord(g_evCR, g_s3);

    // join, then final GEMM
    cudaStreamWaitEvent(0, g_evJoin, 0);
    cudaStreamWaitEvent(0, g_evBC, 0);
    k_main_gemm<<<dim3(HID / 64, (N_NODES + 127) / 128), 256>>>(bgcn, out);

    // rejoin the cursor-reset branch so the capture graph has no dangling work
    cudaStreamWaitEvent(0, g_evCR, 0);
}